// round 2
// baseline (speedup 1.0000x reference)
#include <cuda_runtime.h>

// out[b,c,d] = 0.5 * sum_p W[z(b),c,p] * t[p,b,c,d]   (z(b) = one-hot argmax)
//   t:  [P=4, B, C=256, L=3] fp32   na: [B, Z=64] fp32   W: [Z=64, C=256, P=4]
//   out:[B, C=256, L=3]
//
// HBM-bound streamer (781 MB floor). This version processes 2 nodes per CTA
// with all 8 t-plane float4 loads issued back-to-back (MLP ~8/thread) to keep
// DRAM pipes full; t loads use streaming hint (zero reuse).

#define Z_DIM 64
#define C_DIM 256
#define P_DIM 4
#define L_DIM 3
#define CL    (C_DIM * L_DIM)   // 768 floats per (p,b) plane / out row
#define CP    (C_DIM * P_DIM)   // 1024 floats per W[z] row
#define NTHR  (CL / 4)          // 192 threads: one float4 per thread per node
#define NB    2                 // nodes per CTA

__device__ __forceinline__ float4 ldcs4(const float4* p) {
    float4 v;
    asm volatile("ld.global.cs.v4.f32 {%0,%1,%2,%3}, [%4];"
                 : "=f"(v.x), "=f"(v.y), "=f"(v.z), "=f"(v.w) : "l"(p));
    return v;
}

__global__ void __launch_bounds__(NTHR)
ecwl_kernel(const float* __restrict__ t,
            const float* __restrict__ na,
            const float* __restrict__ W,
            float*       __restrict__ out,
            int B)
{
    __shared__ int s_idx[NB];

    const int b0  = blockIdx.x * NB;
    const int tid = threadIdx.x;

    // Resolve one-hot routing index for both nodes (64 lanes per node).
    if (tid < NB * Z_DIM) {
        const int g    = tid >> 6;        // node within CTA
        const int lane = tid & 63;        // z index
        const int b    = b0 + g;
        if (b < B) {
            float v = na[(size_t)b * Z_DIM + lane];
            if (v > 0.5f) s_idx[g] = lane;
        }
    }
    __syncthreads();

    const int e0 = tid * 4;
    const int c0 = e0 / 3;
    // element -> channel select masks (float4 straddles <=2 channels since L=3)
    const bool s1 = ((e0 + 1) / 3 == c0);
    const bool s2 = ((e0 + 2) / 3 == c0);
    const bool s3 = ((e0 + 3) / 3 == c0);

    const int b1ok = (b0 + 1 < B);

    // Weight rows for both nodes (L2/L1-hot: 64 rows total, reused 50000x).
    const int zi0 = s_idx[0];
    const int zi1 = b1ok ? s_idx[1] : zi0;
    const float4* Wr0 = reinterpret_cast<const float4*>(W + (size_t)zi0 * CP);
    const float4* Wr1 = reinterpret_cast<const float4*>(W + (size_t)zi1 * CP);
    const float4 wa0 = __ldg(Wr0 + c0),     wb0 = __ldg(Wr0 + c0 + 1);
    const float4 wa1 = __ldg(Wr1 + c0),     wb1 = __ldg(Wr1 + c0 + 1);

    const float wA0[4] = {wa0.x, wa0.y, wa0.z, wa0.w};
    const float wB0[4] = {wb0.x, wb0.y, wb0.z, wb0.w};
    const float wA1[4] = {wa1.x, wa1.y, wa1.z, wa1.w};
    const float wB1[4] = {wb1.x, wb1.y, wb1.z, wb1.w};

    // Batch all 8 plane loads (4 per node) for maximum outstanding-load depth.
    float4 v0[P_DIM], v1[P_DIM];
    #pragma unroll
    for (int p = 0; p < P_DIM; ++p) {
        const size_t base = ((size_t)p * B + b0) * CL + e0;
        v0[p] = ldcs4(reinterpret_cast<const float4*>(t + base));
    }
    #pragma unroll
    for (int p = 0; p < P_DIM; ++p) {
        const size_t base = ((size_t)p * B + b0 + (b1ok ? 1 : 0)) * CL + e0;
        v1[p] = ldcs4(reinterpret_cast<const float4*>(t + base));
    }

    float a0 = 0.f, a1 = 0.f, a2 = 0.f, a3 = 0.f;
    float d0 = 0.f, d1 = 0.f, d2 = 0.f, d3 = 0.f;
    #pragma unroll
    for (int p = 0; p < P_DIM; ++p) {
        const float wa = wA0[p], wb = wB0[p];
        a0 += wa * v0[p].x;
        a1 += (s1 ? wa : wb) * v0[p].y;
        a2 += (s2 ? wa : wb) * v0[p].z;
        a3 += (s3 ? wa : wb) * v0[p].w;
    }
    #pragma unroll
    for (int p = 0; p < P_DIM; ++p) {
        const float wa = wA1[p], wb = wB1[p];
        d0 += wa * v1[p].x;
        d1 += (s1 ? wa : wb) * v1[p].y;
        d2 += (s2 ? wa : wb) * v1[p].z;
        d3 += (s3 ? wa : wb) * v1[p].w;
    }

    float4 o0 = {0.5f * a0, 0.5f * a1, 0.5f * a2, 0.5f * a3};
    reinterpret_cast<float4*>(out)[(size_t)b0 * NTHR + tid] = o0;
    if (b1ok) {
        float4 o1 = {0.5f * d0, 0.5f * d1, 0.5f * d2, 0.5f * d3};
        reinterpret_cast<float4*>(out)[(size_t)(b0 + 1) * NTHR + tid] = o1;
    }
}

extern "C" void kernel_launch(void* const* d_in, const int* in_sizes, int n_in,
                              void* d_out, int out_size)
{
    const float* t  = (const float*)d_in[0];   // [P,B,C,L]
    const float* na = (const float*)d_in[1];   // [B,Z]
    const float* W  = (const float*)d_in[2];   // [Z,C,P]
    float* out      = (float*)d_out;           // [B,C,L]

    const int B = in_sizes[1] / Z_DIM;
    const int grid = (B + NB - 1) / NB;

    ecwl_kernel<<<grid, NTHR>>>(t, na, W, out, B);
}

// round 3
// speedup vs baseline: 1.0490x; 1.0490x over previous
#include <cuda_runtime.h>

// out[b,c,d] = 0.5 * sum_p W[z(b),c,p] * t[p,b,c,d]   (z(b) = one-hot argmax)
//   t:  [P=4, B, C=256, L=3] fp32   na: [B, Z=64] fp32   W: [Z=64, C=256, P=4]
//   out:[B, C=256, L=3]
//
// HBM-bound streamer (781 MB floor). R1 shape (1 node/CTA, 192 thr, occ~86%)
// + t-plane loads hoisted ABOVE the one-hot scan/barrier so the na fetch and
// barrier overlap the t stream, + evict-first hint on t (zero reuse).

#define Z_DIM 64
#define C_DIM 256
#define P_DIM 4
#define L_DIM 3
#define CL    (C_DIM * L_DIM)   // 768 floats per (p,b) plane / out row
#define CP    (C_DIM * P_DIM)   // 1024 floats per W[z] row
#define NTHR  (CL / 4)          // 192 threads: one float4 per thread

__device__ __forceinline__ float4 ldcs4(const float* p) {
    float4 v;
    asm volatile("ld.global.cs.v4.f32 {%0,%1,%2,%3}, [%4];"
                 : "=f"(v.x), "=f"(v.y), "=f"(v.z), "=f"(v.w) : "l"(p));
    return v;
}

__global__ void __launch_bounds__(NTHR)
ecwl_kernel(const float* __restrict__ t,
            const float* __restrict__ na,
            const float* __restrict__ W,
            float*       __restrict__ out,
            int B)
{
    __shared__ int s_idx;

    const int b   = blockIdx.x;
    const int tid = threadIdx.x;
    const int e0  = tid * 4;

    // 1) Issue all 4 independent t-plane loads FIRST (addresses don't depend
    //    on the routing index). These fill the DRAM pipe while the na scan
    //    and barrier resolve.
    float4 v[P_DIM];
    #pragma unroll
    for (int p = 0; p < P_DIM; ++p)
        v[p] = ldcs4(t + ((size_t)p * B + b) * CL + e0);

    // 2) Resolve one-hot routing index (exactly one lane writes -> race-free).
    if (tid < Z_DIM) {
        float x = __ldg(na + (size_t)b * Z_DIM + tid);
        if (x > 0.5f) s_idx = tid;
    }
    __syncthreads();
    const int zi = s_idx;

    // 3) Weight row (L1/L2-hot: 64 rows, reused 50000x). float4 = 4 paths of
    //    one channel; a thread's float4 of t straddles <=2 channels (L=3).
    const int c0 = e0 / 3;
    const float4* Wr = reinterpret_cast<const float4*>(W + (size_t)zi * CP);
    const float4 w0 = __ldg(Wr + c0);
    const float4 w1 = __ldg(Wr + c0 + 1);   // c0 <= 254, in-bounds

    const float wA[4] = {w0.x, w0.y, w0.z, w0.w};
    const float wB[4] = {w1.x, w1.y, w1.z, w1.w};

    const bool s1 = ((e0 + 1) / 3 == c0);
    const bool s2 = ((e0 + 2) / 3 == c0);
    const bool s3 = ((e0 + 3) / 3 == c0);

    float a0 = 0.f, a1 = 0.f, a2 = 0.f, a3 = 0.f;
    #pragma unroll
    for (int p = 0; p < P_DIM; ++p) {
        const float wa = wA[p], wb = wB[p];
        a0 += wa * v[p].x;
        a1 += (s1 ? wa : wb) * v[p].y;
        a2 += (s2 ? wa : wb) * v[p].z;
        a3 += (s3 ? wa : wb) * v[p].w;
    }

    float4 o = {0.5f * a0, 0.5f * a1, 0.5f * a2, 0.5f * a3};
    reinterpret_cast<float4*>(out)[(size_t)b * NTHR + tid] = o;
}

extern "C" void kernel_launch(void* const* d_in, const int* in_sizes, int n_in,
                              void* d_out, int out_size)
{
    const float* t  = (const float*)d_in[0];   // [P,B,C,L]
    const float* na = (const float*)d_in[1];   // [B,Z]
    const float* W  = (const float*)d_in[2];   // [Z,C,P]
    float* out      = (float*)d_out;           // [B,C,L]

    const int B = in_sizes[1] / Z_DIM;

    ecwl_kernel<<<B, NTHR>>>(t, na, W, out, B);
}

// round 4
// speedup vs baseline: 1.0908x; 1.0398x over previous
#include <cuda_runtime.h>

// out[b,c,d] = 0.5 * sum_p W[z(b),c,p] * t[p,b,c,d]   (z(b) = one-hot argmax)
//   t:  [P=4, B, C=256, L=3] fp32   na: [B, Z=64] fp32   W: [Z=64, C=256, P=4]
//   out:[B, C=256, L=3]
//
// HBM-bound streamer (781 MB floor). R1 shape (1 node/CTA, 192 thr, 32 regs,
// occ~86%) + t-plane loads hoisted ABOVE the one-hot scan/barrier so the na
// fetch and barrier overlap the t stream. Default cache policy (ld.cs hurt
// graph-replay steady state in R3).

#define Z_DIM 64
#define C_DIM 256
#define P_DIM 4
#define L_DIM 3
#define CL    (C_DIM * L_DIM)   // 768 floats per (p,b) plane / out row
#define CP    (C_DIM * P_DIM)   // 1024 floats per W[z] row
#define NTHR  (CL / 4)          // 192 threads: one float4 per thread

__global__ void __launch_bounds__(NTHR)
ecwl_kernel(const float* __restrict__ t,
            const float* __restrict__ na,
            const float* __restrict__ W,
            float*       __restrict__ out,
            int B)
{
    __shared__ int s_idx;

    const int b   = blockIdx.x;
    const int tid = threadIdx.x;
    const int e0  = tid * 4;

    // 1) Issue all 4 independent t-plane loads FIRST (addresses don't depend
    //    on the routing index). These fill the DRAM pipe while the na scan
    //    and barrier resolve.
    float4 v[P_DIM];
    #pragma unroll
    for (int p = 0; p < P_DIM; ++p)
        v[p] = *reinterpret_cast<const float4*>(t + ((size_t)p * B + b) * CL + e0);

    // 2) Resolve one-hot routing index (exactly one lane writes -> race-free).
    if (tid < Z_DIM) {
        float x = __ldg(na + (size_t)b * Z_DIM + tid);
        if (x > 0.5f) s_idx = tid;
    }
    __syncthreads();
    const int zi = s_idx;

    // 3) Weight row (L1/L2-hot: 64 rows, reused 50000x). float4 = 4 paths of
    //    one channel; a thread's float4 of t straddles <=2 channels (L=3).
    const int c0 = e0 / 3;
    const float4* Wr = reinterpret_cast<const float4*>(W + (size_t)zi * CP);
    const float4 w0 = __ldg(Wr + c0);
    const float4 w1 = __ldg(Wr + c0 + 1);   // c0 <= 254, in-bounds

    const float wA[4] = {w0.x, w0.y, w0.z, w0.w};
    const float wB[4] = {w1.x, w1.y, w1.z, w1.w};

    const bool s1 = ((e0 + 1) / 3 == c0);
    const bool s2 = ((e0 + 2) / 3 == c0);
    const bool s3 = ((e0 + 3) / 3 == c0);

    float a0 = 0.f, a1 = 0.f, a2 = 0.f, a3 = 0.f;
    #pragma unroll
    for (int p = 0; p < P_DIM; ++p) {
        const float wa = wA[p], wb = wB[p];
        a0 += wa * v[p].x;
        a1 += (s1 ? wa : wb) * v[p].y;
        a2 += (s2 ? wa : wb) * v[p].z;
        a3 += (s3 ? wa : wb) * v[p].w;
    }

    float4 o = {0.5f * a0, 0.5f * a1, 0.5f * a2, 0.5f * a3};
    reinterpret_cast<float4*>(out)[(size_t)b * NTHR + tid] = o;
}

extern "C" void kernel_launch(void* const* d_in, const int* in_sizes, int n_in,
                              void* d_out, int out_size)
{
    const float* t  = (const float*)d_in[0];   // [P,B,C,L]
    const float* na = (const float*)d_in[1];   // [B,Z]
    const float* W  = (const float*)d_in[2];   // [Z,C,P]
    float* out      = (float*)d_out;           // [B,C,L]

    const int B = in_sizes[1] / Z_DIM;

    ecwl_kernel<<<B, NTHR>>>(t, na, W, out, B);
}